// round 15
// baseline (speedup 1.0000x reference)
#include <cuda_runtime.h>

#define NB 32
#define HH 640
#define WW 640
#define HW (HH * WW)
#define NCHW (NB * 2 * HW)

#define CH 16                   // batches per chunk
#define NCHUNK (NB / CH)

#define BLK 256
// 2D tile per block: 128 px wide x 8 px tall. Warp = one row; lane L handles
// pixels x0+L+{0,32,64,96} -> every access lane-consecutive (2 wf, 100% line
// utilization) with 4-sample ILP, computed in two groups of 2 to cap regs.
#define TLX 128
#define TLY 8

// Chunk ping-pong scratch, interleaved float2 [CH,H,W,(x,y)].
__device__ float2 g_bufA[CH * HW];
__device__ float2 g_bufB[CH * HW];

// ---------------- Blackwell packed f32x2 helpers ----------------
typedef unsigned long long u64;

__device__ __forceinline__ u64 f2bcast(float a) {
    u64 r; asm("mov.b64 %0, {%1, %1};" : "=l"(r) : "f"(a)); return r;
}
__device__ __forceinline__ u64 f2mul(u64 a, u64 b) {
    u64 r; asm("mul.rn.f32x2 %0, %1, %2;" : "=l"(r) : "l"(a), "l"(b)); return r;
}
__device__ __forceinline__ u64 f2fma(u64 a, u64 b, u64 c) {
    u64 r; asm("fma.rn.f32x2 %0, %1, %2, %3;" : "=l"(r) : "l"(a), "l"(b), "l"(c)); return r;
}
__device__ __forceinline__ float2 f2unpack(u64 a) {
    float2 v; asm("mov.b64 {%0, %1}, %2;" : "=f"(v.x), "=f"(v.y) : "l"(a)); return v;
}

// Bilinear sample (border clamp, align_corners=True) from interleaved field
// b[H*W] at normalized coords (tx,ty). Coordinate math bit-identical to all
// passing rounds; neighbor indices integer-exact offset form; lerp uses
// mul+FFMA2 (single-rounded adds -> incoherent ulp-class drift only).
__device__ __forceinline__ float2 samp(const float2* __restrict__ b,
                                       float tx, float ty) {
    float px = (tx + 1.0f) * (0.5f * (float)(WW - 1));
    float py = (ty + 1.0f) * (0.5f * (float)(HH - 1));
    px = fminf(fmaxf(px, 0.0f), (float)(WW - 1));
    py = fminf(fmaxf(py, 0.0f), (float)(HH - 1));
    float x0f = floorf(px);
    float y0f = floorf(py);
    int x0 = (int)x0f;
    int y0 = (int)y0f;
    float wx = px - x0f;
    float wy = py - y0f;

    int dxo = (x0 < WW - 1) ? 1 : 0;      // == min(x0+1,W-1) - x0
    int dyo = (y0 < HH - 1) ? WW : 0;     // == (min(y0+1,H-1) - y0)*WW
    int a00 = y0 * WW + x0;

    const u64* bb = reinterpret_cast<const u64*>(b);
    u64 v00 = bb[a00];
    u64 v01 = bb[a00 + dxo];
    u64 v10 = bb[a00 + dyo];
    u64 v11 = bb[a00 + dyo + dxo];

    u64 wx2 = f2bcast(wx);
    u64 ox2 = f2bcast(1.0f - wx);
    u64 wy2 = f2bcast(wy);
    u64 oy2 = f2bcast(1.0f - wy);

    u64 top = f2fma(wx2, v01, f2mul(ox2, v00));
    u64 bot = f2fma(wx2, v11, f2mul(ox2, v10));
    u64 res = f2fma(wy2, bot, f2mul(oy2, top));
    return f2unpack(res);
}

// Planar sampler over v with scale S applied to each tap (step 0 only; kept
// in the original scalar form).
__device__ __forceinline__ float2 sampP(const float* __restrict__ vx,
                                        const float* __restrict__ vy,
                                        float tx, float ty, float S) {
    float px = (tx + 1.0f) * (0.5f * (float)(WW - 1));
    float py = (ty + 1.0f) * (0.5f * (float)(HH - 1));
    px = fminf(fmaxf(px, 0.0f), (float)(WW - 1));
    py = fminf(fmaxf(py, 0.0f), (float)(HH - 1));
    float x0f = floorf(px);
    float y0f = floorf(py);
    int x0 = (int)x0f;
    int y0 = (int)y0f;
    int x1 = min(x0 + 1, WW - 1);
    int y1 = min(y0 + 1, HH - 1);
    float wx = px - x0f;
    float wy = py - y0f;
    float sx, sy;
    {
        float a00 = vx[y0 * WW + x0] * S, a01 = vx[y0 * WW + x1] * S;
        float a10 = vx[y1 * WW + x0] * S, a11 = vx[y1 * WW + x1] * S;
        float top = a00 * (1.0f - wx) + a01 * wx;
        float bot = a10 * (1.0f - wx) + a11 * wx;
        sx = top * (1.0f - wy) + bot * wy;
    }
    {
        float a00 = vy[y0 * WW + x0] * S, a01 = vy[y0 * WW + x1] * S;
        float a10 = vy[y1 * WW + x0] * S, a11 = vy[y1 * WW + x1] * S;
        float top = a00 * (1.0f - wx) + a01 * wx;
        float bot = a10 * (1.0f - wx) + a11 * wx;
        sy = top * (1.0f - wy) + bot * wy;
    }
    return make_float2(sx, sy);
}

// Step 0: disp0 = v*2^-32, one step, write interleaved.
__global__ __launch_bounds__(BLK, 7) void k_first(const float* __restrict__ v,
                                                  const float2* __restrict__ idg,
                                                  float2* __restrict__ dst) {
    int n = blockIdx.z;
    int y = blockIdx.y * TLY + threadIdx.y;
    int x = blockIdx.x * TLX + threadIdx.x;
    int p = y * WW + x;
    const float* vx = v + (size_t)n * 2 * HW;
    const float* vy = vx + HW;
    const float S = 0x1p-32f;
    float2* o = dst + (size_t)n * HW;

#pragma unroll
    for (int k = 0; k < 4; ++k) {
        int pi = p + k * 32;
        float2 g = idg[pi];
        float dx = vx[pi] * S;
        float dy = vy[pi] * S;
        float2 s = sampP(vx, vy, g.x + dx, g.y + dy, S);
        o[pi] = make_float2(dx + s.x, dy + s.y);
    }
}

// Middle steps: interleaved -> interleaved ping-pong; batched d/g loads,
// sampling in two groups of 2 to cap live registers.
__global__ __launch_bounds__(BLK, 7) void k_step(const float2* __restrict__ src,
                                                 const float2* __restrict__ idg,
                                                 float2* __restrict__ dst) {
    int n = blockIdx.z;
    int y = blockIdx.y * TLY + threadIdx.y;
    int x = blockIdx.x * TLX + threadIdx.x;
    int p = y * WW + x;
    const float2* b = src + (size_t)n * HW;
    float2* o = dst + (size_t)n * HW;

    float2 d[4], g[4];
#pragma unroll
    for (int k = 0; k < 4; ++k) {
        d[k] = b[p + k * 32];
        g[k] = idg[p + k * 32];
    }

    // Group 0: samples 0,1
    {
        float2 s0 = samp(b, g[0].x + d[0].x, g[0].y + d[0].y);
        float2 s1 = samp(b, g[1].x + d[1].x, g[1].y + d[1].y);
        o[p]      = make_float2(d[0].x + s0.x, d[0].y + s0.y);
        o[p + 32] = make_float2(d[1].x + s1.x, d[1].y + s1.y);
    }
    // Group 1: samples 2,3
    {
        float2 s2 = samp(b, g[2].x + d[2].x, g[2].y + d[2].y);
        float2 s3 = samp(b, g[3].x + d[3].x, g[3].y + d[3].y);
        o[p + 64] = make_float2(d[2].x + s2.x, d[2].y + s2.y);
        o[p + 96] = make_float2(d[3].x + s3.x, d[3].y + s3.y);
    }
}

// Final step: step + planar output write.
//   out[0:NCHW)      = transformation = idgrid + disp
//   out[NCHW:2*NCHW) = displacement
__global__ __launch_bounds__(BLK, 7) void k_last(const float2* __restrict__ src,
                                                 const float2* __restrict__ idg,
                                                 float* __restrict__ out,
                                                 int nglobBase) {
    int n = blockIdx.z;
    int y = blockIdx.y * TLY + threadIdx.y;
    int x = blockIdx.x * TLX + threadIdx.x;
    int p = y * WW + x;
    const float2* b = src + (size_t)n * HW;
    size_t base = (size_t)(nglobBase + n) * 2 * HW;

#pragma unroll
    for (int k = 0; k < 4; ++k) {
        int pi = p + k * 32;
        float2 d = b[pi];
        float2 g = idg[pi];
        float2 s = samp(b, g.x + d.x, g.y + d.y);
        float nx = d.x + s.x;
        float ny = d.y + s.y;
        out[base + pi]             = g.x + nx;  // transformation ch0
        out[base + HW + pi]        = g.y + ny;  // transformation ch1
        out[NCHW + base + pi]      = nx;        // displacement ch0
        out[NCHW + base + HW + pi] = ny;        // displacement ch1
    }
}

extern "C" void kernel_launch(void* const* d_in, const int* in_sizes, int n_in,
                              void* d_out, int out_size) {
    const float* v = (const float*)d_in[0];
    const float2* idg = (const float2*)d_in[1];  // [1,H,W,2] interleaved
    float* out = (float*)d_out;

    float2 *A, *B;
    cudaGetSymbolAddress((void**)&A, g_bufA);
    cudaGetSymbolAddress((void**)&B, g_bufB);

    dim3 threads(32, 8);
    dim3 blocks(WW / TLX, HH / TLY, CH);     // 5 x 80 x 16 = 6400 blocks

    for (int c = 0; c < NCHUNK; ++c) {
        const float* vC = v + (size_t)c * CH * 2 * HW;

        // Step 0 (reads v planar, scale folded) -> A
        k_first<<<blocks, threads>>>(vC, idg, A);

        // Steps 1..30 ping-pong
        float2* src = A;
        float2* dst = B;
        for (int it = 1; it <= 30; ++it) {
            k_step<<<blocks, threads>>>(src, idg, dst);
            float2* t = src; src = dst; dst = t;
        }
        // After 30 steps result is in src (== A)

        // Step 31 fused with planar output write
        k_last<<<blocks, threads>>>(src, idg, out, c * CH);
    }
}

// round 16
// speedup vs baseline: 1.0177x; 1.0177x over previous
#include <cuda_runtime.h>

#define NB 32
#define HH 640
#define WW 640
#define HW (HH * WW)
#define NCHW (NB * 2 * HW)

#define CH 16                   // batches per chunk
#define NCHUNK (NB / CH)

#define BLK 256
// 2D tile per block: 128 px wide x 8 px tall. Warp = one row; lane L handles
// pixels x0+L+{0,32,64,96} -> every access lane-consecutive (2 wf, 100% line
// utilization) with 4-sample ILP, computed in two groups of 2 to cap regs.
#define TLX 128
#define TLY 8

// Chunk ping-pong scratch, interleaved float2 [CH,H,W,(x,y)].
__device__ float2 g_bufA[CH * HW];
__device__ float2 g_bufB[CH * HW];

// ---------------- Blackwell packed f32x2 helpers ----------------
typedef unsigned long long u64;

__device__ __forceinline__ u64 f2bcast(float a) {
    u64 r; asm("mov.b64 %0, {%1, %1};" : "=l"(r) : "f"(a)); return r;
}
__device__ __forceinline__ u64 f2mul(u64 a, u64 b) {
    u64 r; asm("mul.rn.f32x2 %0, %1, %2;" : "=l"(r) : "l"(a), "l"(b)); return r;
}
__device__ __forceinline__ u64 f2add(u64 a, u64 b) {
    u64 r; asm("add.rn.f32x2 %0, %1, %2;" : "=l"(r) : "l"(a), "l"(b)); return r;
}
__device__ __forceinline__ float2 f2unpack(u64 a) {
    float2 v; asm("mov.b64 {%0, %1}, %2;" : "=f"(v.x), "=f"(v.y) : "l"(a)); return v;
}

// Bilinear sample (border clamp, align_corners=True) from interleaved field
// b[H*W] at normalized coords (tx,ty). EXACT round-14 arithmetic (best).
__device__ __forceinline__ float2 samp(const float2* __restrict__ b,
                                       float tx, float ty) {
    float px = (tx + 1.0f) * (0.5f * (float)(WW - 1));
    float py = (ty + 1.0f) * (0.5f * (float)(HH - 1));
    px = fminf(fmaxf(px, 0.0f), (float)(WW - 1));
    py = fminf(fmaxf(py, 0.0f), (float)(HH - 1));
    float x0f = floorf(px);
    float y0f = floorf(py);
    int x0 = (int)x0f;
    int y0 = (int)y0f;
    int x1 = min(x0 + 1, WW - 1);
    int y1 = min(y0 + 1, HH - 1);
    float wx = px - x0f;
    float wy = py - y0f;

    const u64* bb = reinterpret_cast<const u64*>(b);
    u64 v00 = bb[y0 * WW + x0];
    u64 v01 = bb[y0 * WW + x1];
    u64 v10 = bb[y1 * WW + x0];
    u64 v11 = bb[y1 * WW + x1];

    u64 wx2 = f2bcast(wx);
    u64 ox2 = f2bcast(1.0f - wx);
    u64 wy2 = f2bcast(wy);
    u64 oy2 = f2bcast(1.0f - wy);

    u64 top = f2add(f2mul(v00, ox2), f2mul(v01, wx2));
    u64 bot = f2add(f2mul(v10, ox2), f2mul(v11, wx2));
    u64 res = f2add(f2mul(top, oy2), f2mul(bot, wy2));
    return f2unpack(res);
}

// Planar sampler over v with scale S applied to each tap (step 0 only).
__device__ __forceinline__ float2 sampP(const float* __restrict__ vx,
                                        const float* __restrict__ vy,
                                        float tx, float ty, float S) {
    float px = (tx + 1.0f) * (0.5f * (float)(WW - 1));
    float py = (ty + 1.0f) * (0.5f * (float)(HH - 1));
    px = fminf(fmaxf(px, 0.0f), (float)(WW - 1));
    py = fminf(fmaxf(py, 0.0f), (float)(HH - 1));
    float x0f = floorf(px);
    float y0f = floorf(py);
    int x0 = (int)x0f;
    int y0 = (int)y0f;
    int x1 = min(x0 + 1, WW - 1);
    int y1 = min(y0 + 1, HH - 1);
    float wx = px - x0f;
    float wy = py - y0f;
    float sx, sy;
    {
        float a00 = vx[y0 * WW + x0] * S, a01 = vx[y0 * WW + x1] * S;
        float a10 = vx[y1 * WW + x0] * S, a11 = vx[y1 * WW + x1] * S;
        float top = a00 * (1.0f - wx) + a01 * wx;
        float bot = a10 * (1.0f - wx) + a11 * wx;
        sx = top * (1.0f - wy) + bot * wy;
    }
    {
        float a00 = vy[y0 * WW + x0] * S, a01 = vy[y0 * WW + x1] * S;
        float a10 = vy[y1 * WW + x0] * S, a11 = vy[y1 * WW + x1] * S;
        float top = a00 * (1.0f - wx) + a01 * wx;
        float bot = a10 * (1.0f - wx) + a11 * wx;
        sy = top * (1.0f - wy) + bot * wy;
    }
    return make_float2(sx, sy);
}

// Step 0: disp0 = v*2^-32, one step, write interleaved.
__global__ __launch_bounds__(BLK, 7) void k_first(const float* __restrict__ v,
                                                  const float2* __restrict__ idg,
                                                  float2* __restrict__ dst) {
    int n = blockIdx.z;
    int y = blockIdx.y * TLY + threadIdx.y;
    int x = blockIdx.x * TLX + threadIdx.x;
    int p = y * WW + x;
    const float* vx = v + (size_t)n * 2 * HW;
    const float* vy = vx + HW;
    const float S = 0x1p-32f;
    float2* o = dst + (size_t)n * HW;

#pragma unroll
    for (int k = 0; k < 4; ++k) {
        int pi = p + k * 32;
        float2 g = idg[pi];
        float dx = vx[pi] * S;
        float dy = vy[pi] * S;
        float2 s = sampP(vx, vy, g.x + dx, g.y + dy, S);
        o[pi] = make_float2(dx + s.x, dy + s.y);
    }
}

// Middle steps: interleaved -> interleaved ping-pong; batched d/g loads,
// sampling in two groups of 2 to cap live registers. 8 blocks/SM (100% occ).
__global__ __launch_bounds__(BLK, 8) void k_step(const float2* __restrict__ src,
                                                 const float2* __restrict__ idg,
                                                 float2* __restrict__ dst) {
    int n = blockIdx.z;
    int y = blockIdx.y * TLY + threadIdx.y;
    int x = blockIdx.x * TLX + threadIdx.x;
    int p = y * WW + x;
    const float2* b = src + (size_t)n * HW;
    float2* o = dst + (size_t)n * HW;

    float2 d[4], g[4];
#pragma unroll
    for (int k = 0; k < 4; ++k) {
        d[k] = b[p + k * 32];
        g[k] = idg[p + k * 32];
    }

    // Group 0: samples 0,1
    {
        float2 s0 = samp(b, g[0].x + d[0].x, g[0].y + d[0].y);
        float2 s1 = samp(b, g[1].x + d[1].x, g[1].y + d[1].y);
        o[p]      = make_float2(d[0].x + s0.x, d[0].y + s0.y);
        o[p + 32] = make_float2(d[1].x + s1.x, d[1].y + s1.y);
    }
    // Group 1: samples 2,3
    {
        float2 s2 = samp(b, g[2].x + d[2].x, g[2].y + d[2].y);
        float2 s3 = samp(b, g[3].x + d[3].x, g[3].y + d[3].y);
        o[p + 64] = make_float2(d[2].x + s2.x, d[2].y + s2.y);
        o[p + 96] = make_float2(d[3].x + s3.x, d[3].y + s3.y);
    }
}

// Final step: step + planar output write.
//   out[0:NCHW)      = transformation = idgrid + disp
//   out[NCHW:2*NCHW) = displacement
__global__ __launch_bounds__(BLK, 7) void k_last(const float2* __restrict__ src,
                                                 const float2* __restrict__ idg,
                                                 float* __restrict__ out,
                                                 int nglobBase) {
    int n = blockIdx.z;
    int y = blockIdx.y * TLY + threadIdx.y;
    int x = blockIdx.x * TLX + threadIdx.x;
    int p = y * WW + x;
    const float2* b = src + (size_t)n * HW;
    size_t base = (size_t)(nglobBase + n) * 2 * HW;

#pragma unroll
    for (int k = 0; k < 4; ++k) {
        int pi = p + k * 32;
        float2 d = b[pi];
        float2 g = idg[pi];
        float2 s = samp(b, g.x + d.x, g.y + d.y);
        float nx = d.x + s.x;
        float ny = d.y + s.y;
        out[base + pi]             = g.x + nx;  // transformation ch0
        out[base + HW + pi]        = g.y + ny;  // transformation ch1
        out[NCHW + base + pi]      = nx;        // displacement ch0
        out[NCHW + base + HW + pi] = ny;        // displacement ch1
    }
}

extern "C" void kernel_launch(void* const* d_in, const int* in_sizes, int n_in,
                              void* d_out, int out_size) {
    const float* v = (const float*)d_in[0];
    const float2* idg = (const float2*)d_in[1];  // [1,H,W,2] interleaved
    float* out = (float*)d_out;

    float2 *A, *B;
    cudaGetSymbolAddress((void**)&A, g_bufA);
    cudaGetSymbolAddress((void**)&B, g_bufB);

    dim3 threads(32, 8);
    dim3 blocks(WW / TLX, HH / TLY, CH);     // 5 x 80 x 16 = 6400 blocks

    for (int c = 0; c < NCHUNK; ++c) {
        const float* vC = v + (size_t)c * CH * 2 * HW;

        // Step 0 (reads v planar, scale folded) -> A
        k_first<<<blocks, threads>>>(vC, idg, A);

        // Steps 1..30 ping-pong
        float2* src = A;
        float2* dst = B;
        for (int it = 1; it <= 30; ++it) {
            k_step<<<blocks, threads>>>(src, idg, dst);
            float2* t = src; src = dst; dst = t;
        }
        // After 30 steps result is in src (== A)

        // Step 31 fused with planar output write
        k_last<<<blocks, threads>>>(src, idg, out, c * CH);
    }
}

// round 17
// speedup vs baseline: 1.0179x; 1.0002x over previous
#include <cuda_runtime.h>

#define NB 32
#define HH 640
#define WW 640
#define HW (HH * WW)
#define NCHW (NB * 2 * HW)

#define CH 16                   // batches per chunk
#define NCHUNK (NB / CH)

#define BLK 256
// 2D tile per block: 128 px wide x 8 px tall. Warp = one row; lane L handles
// pixels x0+L+{0,32,64,96} -> every access lane-consecutive (2 wf, 100% line
// utilization) with 4-sample ILP, computed in two groups of 2 to cap regs.
#define TLX 128
#define TLY 8

// Chunk ping-pong scratch, interleaved float2 [CH,H,W,(x,y)].
__device__ float2 g_bufA[CH * HW];
__device__ float2 g_bufB[CH * HW];

// Separable identity grid tables (exact floats copied from the input grid:
// idg[y*WW+x] == (g_gx[x], g_gy[y]) since the grid is a meshgrid).
__device__ float g_gx[WW];
__device__ float g_gy[HH];

// ---------------- Blackwell packed f32x2 helpers ----------------
typedef unsigned long long u64;

__device__ __forceinline__ u64 f2bcast(float a) {
    u64 r; asm("mov.b64 %0, {%1, %1};" : "=l"(r) : "f"(a)); return r;
}
__device__ __forceinline__ u64 f2mul(u64 a, u64 b) {
    u64 r; asm("mul.rn.f32x2 %0, %1, %2;" : "=l"(r) : "l"(a), "l"(b)); return r;
}
__device__ __forceinline__ u64 f2add(u64 a, u64 b) {
    u64 r; asm("add.rn.f32x2 %0, %1, %2;" : "=l"(r) : "l"(a), "l"(b)); return r;
}
__device__ __forceinline__ float2 f2unpack(u64 a) {
    float2 v; asm("mov.b64 {%0, %1}, %2;" : "=f"(v.x), "=f"(v.y) : "l"(a)); return v;
}

// Bilinear sample (border clamp, align_corners=True) from interleaved field
// b[H*W] at normalized coords (tx,ty). EXACT round-14 arithmetic (best).
__device__ __forceinline__ float2 samp(const float2* __restrict__ b,
                                       float tx, float ty) {
    float px = (tx + 1.0f) * (0.5f * (float)(WW - 1));
    float py = (ty + 1.0f) * (0.5f * (float)(HH - 1));
    px = fminf(fmaxf(px, 0.0f), (float)(WW - 1));
    py = fminf(fmaxf(py, 0.0f), (float)(HH - 1));
    float x0f = floorf(px);
    float y0f = floorf(py);
    int x0 = (int)x0f;
    int y0 = (int)y0f;
    int x1 = min(x0 + 1, WW - 1);
    int y1 = min(y0 + 1, HH - 1);
    float wx = px - x0f;
    float wy = py - y0f;

    const u64* bb = reinterpret_cast<const u64*>(b);
    u64 v00 = bb[y0 * WW + x0];
    u64 v01 = bb[y0 * WW + x1];
    u64 v10 = bb[y1 * WW + x0];
    u64 v11 = bb[y1 * WW + x1];

    u64 wx2 = f2bcast(wx);
    u64 ox2 = f2bcast(1.0f - wx);
    u64 wy2 = f2bcast(wy);
    u64 oy2 = f2bcast(1.0f - wy);

    u64 top = f2add(f2mul(v00, ox2), f2mul(v01, wx2));
    u64 bot = f2add(f2mul(v10, ox2), f2mul(v11, wx2));
    u64 res = f2add(f2mul(top, oy2), f2mul(bot, wy2));
    return f2unpack(res);
}

// Planar sampler over v with scale S applied to each tap (step 0 only).
__device__ __forceinline__ float2 sampP(const float* __restrict__ vx,
                                        const float* __restrict__ vy,
                                        float tx, float ty, float S) {
    float px = (tx + 1.0f) * (0.5f * (float)(WW - 1));
    float py = (ty + 1.0f) * (0.5f * (float)(HH - 1));
    px = fminf(fmaxf(px, 0.0f), (float)(WW - 1));
    py = fminf(fmaxf(py, 0.0f), (float)(HH - 1));
    float x0f = floorf(px);
    float y0f = floorf(py);
    int x0 = (int)x0f;
    int y0 = (int)y0f;
    int x1 = min(x0 + 1, WW - 1);
    int y1 = min(y0 + 1, HH - 1);
    float wx = px - x0f;
    float wy = py - y0f;
    float sx, sy;
    {
        float a00 = vx[y0 * WW + x0] * S, a01 = vx[y0 * WW + x1] * S;
        float a10 = vx[y1 * WW + x0] * S, a11 = vx[y1 * WW + x1] * S;
        float top = a00 * (1.0f - wx) + a01 * wx;
        float bot = a10 * (1.0f - wx) + a11 * wx;
        sx = top * (1.0f - wy) + bot * wy;
    }
    {
        float a00 = vy[y0 * WW + x0] * S, a01 = vy[y0 * WW + x1] * S;
        float a10 = vy[y1 * WW + x0] * S, a11 = vy[y1 * WW + x1] * S;
        float top = a00 * (1.0f - wx) + a01 * wx;
        float bot = a10 * (1.0f - wx) + a11 * wx;
        sy = top * (1.0f - wy) + bot * wy;
    }
    return make_float2(sx, sy);
}

// Extract the separable grid tables from the input grid (exact float copy).
__global__ void k_fill(const float2* __restrict__ idg) {
    int i = blockIdx.x * blockDim.x + threadIdx.x;
    if (i < WW) g_gx[i] = idg[i].x;
    if (i < HH) g_gy[i] = idg[(size_t)i * WW].y;
}

// Step 0: disp0 = v*2^-32, one step, write interleaved.
__global__ __launch_bounds__(BLK, 7) void k_first(const float* __restrict__ v,
                                                  float2* __restrict__ dst) {
    int n = blockIdx.z;
    int y = blockIdx.y * TLY + threadIdx.y;
    int x = blockIdx.x * TLX + threadIdx.x;
    int p = y * WW + x;
    const float* vx = v + (size_t)n * 2 * HW;
    const float* vy = vx + HW;
    const float S = 0x1p-32f;
    float2* o = dst + (size_t)n * HW;

    float gy = g_gy[y];
#pragma unroll
    for (int k = 0; k < 4; ++k) {
        int pi = p + k * 32;
        float gx = g_gx[x + k * 32];
        float dx = vx[pi] * S;
        float dy = vy[pi] * S;
        float2 s = sampP(vx, vy, gx + dx, gy + dy, S);
        o[pi] = make_float2(dx + s.x, dy + s.y);
    }
}

// Middle steps: interleaved -> interleaved ping-pong; batched d loads,
// separable grid tables (gy warp-broadcast, gx lane-consecutive 4B),
// sampling in two groups of 2 to cap live registers.
__global__ __launch_bounds__(BLK, 8) void k_step(const float2* __restrict__ src,
                                                 float2* __restrict__ dst) {
    int n = blockIdx.z;
    int y = blockIdx.y * TLY + threadIdx.y;
    int x = blockIdx.x * TLX + threadIdx.x;
    int p = y * WW + x;
    const float2* b = src + (size_t)n * HW;
    float2* o = dst + (size_t)n * HW;

    float gy = g_gy[y];
    float2 d[4];
    float gxv[4];
#pragma unroll
    for (int k = 0; k < 4; ++k) {
        d[k] = b[p + k * 32];
        gxv[k] = g_gx[x + k * 32];
    }

    // Group 0: samples 0,1
    {
        float2 s0 = samp(b, gxv[0] + d[0].x, gy + d[0].y);
        float2 s1 = samp(b, gxv[1] + d[1].x, gy + d[1].y);
        o[p]      = make_float2(d[0].x + s0.x, d[0].y + s0.y);
        o[p + 32] = make_float2(d[1].x + s1.x, d[1].y + s1.y);
    }
    // Group 1: samples 2,3
    {
        float2 s2 = samp(b, gxv[2] + d[2].x, gy + d[2].y);
        float2 s3 = samp(b, gxv[3] + d[3].x, gy + d[3].y);
        o[p + 64] = make_float2(d[2].x + s2.x, d[2].y + s2.y);
        o[p + 96] = make_float2(d[3].x + s3.x, d[3].y + s3.y);
    }
}

// Final step: step + planar output write.
//   out[0:NCHW)      = transformation = idgrid + disp
//   out[NCHW:2*NCHW) = displacement
__global__ __launch_bounds__(BLK, 7) void k_last(const float2* __restrict__ src,
                                                 float* __restrict__ out,
                                                 int nglobBase) {
    int n = blockIdx.z;
    int y = blockIdx.y * TLY + threadIdx.y;
    int x = blockIdx.x * TLX + threadIdx.x;
    int p = y * WW + x;
    const float2* b = src + (size_t)n * HW;
    size_t base = (size_t)(nglobBase + n) * 2 * HW;

    float gy = g_gy[y];
#pragma unroll
    for (int k = 0; k < 4; ++k) {
        int pi = p + k * 32;
        float gx = g_gx[x + k * 32];
        float2 d = b[pi];
        float2 s = samp(b, gx + d.x, gy + d.y);
        float nx = d.x + s.x;
        float ny = d.y + s.y;
        out[base + pi]             = gx + nx;   // transformation ch0
        out[base + HW + pi]        = gy + ny;   // transformation ch1
        out[NCHW + base + pi]      = nx;        // displacement ch0
        out[NCHW + base + HW + pi] = ny;        // displacement ch1
    }
}

extern "C" void kernel_launch(void* const* d_in, const int* in_sizes, int n_in,
                              void* d_out, int out_size) {
    const float* v = (const float*)d_in[0];
    const float2* idg = (const float2*)d_in[1];  // [1,H,W,2] interleaved
    float* out = (float*)d_out;

    float2 *A, *B;
    cudaGetSymbolAddress((void**)&A, g_bufA);
    cudaGetSymbolAddress((void**)&B, g_bufB);

    dim3 threads(32, 8);
    dim3 blocks(WW / TLX, HH / TLY, CH);     // 5 x 80 x 16 = 6400 blocks

    // Extract separable grid tables (exact float copies from idg).
    k_fill<<<(WW + 255) / 256, 256>>>(idg);

    for (int c = 0; c < NCHUNK; ++c) {
        const float* vC = v + (size_t)c * CH * 2 * HW;

        // Step 0 (reads v planar, scale folded) -> A
        k_first<<<blocks, threads>>>(vC, A);

        // Steps 1..30 ping-pong
        float2* src = A;
        float2* dst = B;
        for (int it = 1; it <= 30; ++it) {
            k_step<<<blocks, threads>>>(src, dst);
            float2* t = src; src = dst; dst = t;
        }
        // After 30 steps result is in src (== A)

        // Step 31 fused with planar output write
        k_last<<<blocks, threads>>>(src, out, c * CH);
    }
}